// round 17
// baseline (speedup 1.0000x reference)
#include <cuda_runtime.h>
#include <cstdint>

// Problem dims (fixed by the dataset)
#define T_DIM 128
#define B_DIM 64
#define H_DIM 1024
#define M_DIM (T_DIM * B_DIM)   // 8192
#define BH    (B_DIM * H_DIM)   // 65536

#define DELTA 1e-3f

// Scratch (allocation-free rule: __device__ globals)
__device__ float g_xfix[(size_t)B_DIM * 1024 * T_DIM]; // 32 MB exact xcol per flagged slot
__device__ float g_xproj[(size_t)M_DIM * H_DIM];       // 32 MB approx x_proj
__device__ float g_spk[(size_t)M_DIM * H_DIM];         // 32 MB spikes
__device__ float g_w1t[(size_t)H_DIM * H_DIM];         // 4 MB tf32-rounded W1
__device__ float g_w2t[(size_t)H_DIM * H_DIM];         // 4 MB tf32-rounded W2
__device__ int   g_cnt[B_DIM];
__device__ int   g_list[B_DIM * H_DIM];

// ============================================================================
// Helpers
// ============================================================================
__device__ __forceinline__ uint32_t smem_u32(const void* p) {
    uint32_t a;
    asm("{ .reg .u64 t; cvta.to.shared.u64 t, %1; cvt.u32.u64 %0, t; }"
        : "=r"(a) : "l"(p));
    return a;
}
__device__ __forceinline__ void cp_async16(uint32_t dst, const void* src) {
    asm volatile("cp.async.cg.shared.global [%0], [%1], 16;"
                 :: "r"(dst), "l"(src) : "memory");
}
#define CP_ASYNC_COMMIT() asm volatile("cp.async.commit_group;" ::: "memory")
#define CP_ASYNC_WAIT(n)  asm volatile("cp.async.wait_group %0;" :: "n"(n) : "memory")

__device__ __forceinline__ void mma_tf32(float* d, const uint32_t* a, const uint32_t* b) {
    asm volatile(
        "mma.sync.aligned.m16n8k8.row.col.f32.tf32.tf32.f32 "
        "{%0,%1,%2,%3}, {%4,%5,%6,%7}, {%8,%9}, {%0,%1,%2,%3};"
        : "+f"(d[0]), "+f"(d[1]), "+f"(d[2]), "+f"(d[3])
        : "r"(a[0]), "r"(a[1]), "r"(a[2]), "r"(a[3]),
          "r"(b[0]), "r"(b[1]));
}

// ============================================================================
// TF32 tensor-core NT-GEMM with FRAGMENT DOUBLE-BUFFERING:
// C = A * B^T. CTA 128x128, BK=32, 128 threads (4 warps, 64x64 warp tiles),
// 2 CTAs/SM, 3-stage cp.async smem pipeline, XOR-swizzled smem.
// ks-loop loads fragments for ks+1 while the MMAs of ks drain, hiding the
// 29-cyc LDS latency that 2 warps/SMSP cannot cover by TLP alone.
// A may be raw fp32 (HW RZ-truncates); B should be pre-rounded tf32.
// ============================================================================
#define BM        128
#define BN        128
#define BKF       32
#define A_U32     (BM * BKF)
#define B_U32     (BN * BKF)
#define STAGE_U32 (A_U32 + B_U32)
#define STAGE_BYTES (STAGE_U32 * 4)
#define NSTAGE    3
#define SMEM_DYN  (NSTAGE * STAGE_BYTES)   // 96 KB
#define NT_GEMM   128

__global__ void __launch_bounds__(NT_GEMM, 2)
gemm_tf32_mma(const float* __restrict__ A,
              const float* __restrict__ Bm,
              float* __restrict__ C)
{
    extern __shared__ float sm[];
    const uint32_t smu = smem_u32(sm);

    const int tid  = threadIdx.x;
    const int lane = tid & 31;
    const int wid  = tid >> 5;
    const int g = lane >> 2;
    const int t = lane & 3;
    const int wm = (wid >> 1) * 64;
    const int wn = (wid & 1) * 64;

    const int m0 = blockIdx.y * BM;
    const int n0 = blockIdx.x * BN;

    const float* Abase = A  + (size_t)m0 * H_DIM;
    const float* Bbase = Bm + (size_t)n0 * H_DIM;

    int lra[8], lqa[8];
    uint32_t sda[8];
#pragma unroll
    for (int p = 0; p < 8; p++) {
        int f = tid + p * NT_GEMM;
        lra[p] = f >> 3;
        lqa[p] = f & 7;
        sda[p] = (uint32_t)((lra[p] * 32 + ((lqa[p] ^ (lra[p] & 7)) << 2)) * 4);
    }

    float acc[4][8][4];
#pragma unroll
    for (int i = 0; i < 4; i++)
#pragma unroll
        for (int j = 0; j < 8; j++)
#pragma unroll
            for (int r = 0; r < 4; r++) acc[i][j][r] = 0.0f;

    auto prefetch = [&](int chunk, int stage) {
        const uint32_t base = smu + (uint32_t)stage * STAGE_BYTES;
#pragma unroll
        for (int p = 0; p < 8; p++)
            cp_async16(base + sda[p],
                       Abase + (size_t)lra[p] * H_DIM + chunk * BKF + lqa[p] * 4);
#pragma unroll
        for (int p = 0; p < 8; p++)
            cp_async16(base + (uint32_t)(A_U32 * 4) + sda[p],
                       Bbase + (size_t)lra[p] * H_DIM + chunk * BKF + lqa[p] * 4);
    };

    const int NCH = H_DIM / BKF;
    prefetch(0, 0);
    CP_ASYNC_COMMIT();
    prefetch(1, 1);
    CP_ASYNC_COMMIT();

    uint32_t af[2][4][4];   // fragment double buffer
    uint32_t bf[2][8][2];

    int stage = 0;
    for (int it = 0; it < NCH; ++it) {
        if (it + 1 < NCH) { CP_ASYNC_WAIT(1); } else { CP_ASYNC_WAIT(0); }
        __syncthreads();
        if (it + 2 < NCH) {
            int s2 = stage + 2; if (s2 >= NSTAGE) s2 -= NSTAGE;
            prefetch(it + 2, s2);
            CP_ASYNC_COMMIT();
        }

        const uint32_t* As = (const uint32_t*)sm + (size_t)stage * STAGE_U32;
        const uint32_t* Bs = As + A_U32;

        // Load fragments for ks = 0 into buffer 0.
        {
            const int c0 = (0 ^ g) << 2;
            const int c1 = (1 ^ g) << 2;
#pragma unroll
            for (int mt = 0; mt < 4; mt++) {
                const int mb = wm + mt * 16 + g;
                af[0][mt][0] = As[mb * 32 + c0 + t];
                af[0][mt][1] = As[(mb + 8) * 32 + c0 + t];
                af[0][mt][2] = As[mb * 32 + c1 + t];
                af[0][mt][3] = As[(mb + 8) * 32 + c1 + t];
            }
#pragma unroll
            for (int nt = 0; nt < 8; nt++) {
                const int nb = wn + nt * 8 + g;
                bf[0][nt][0] = Bs[nb * 32 + c0 + t];
                bf[0][nt][1] = Bs[nb * 32 + c1 + t];
            }
        }

#pragma unroll
        for (int ks = 0; ks < 4; ks++) {
            const int cur = ks & 1;
            const int nxt = cur ^ 1;
            // Prefetch fragments for ks+1 while MMAs of ks drain.
            if (ks < 3) {
                const int c0 = (((ks + 1) * 2) ^ g) << 2;
                const int c1 = (((ks + 1) * 2 + 1) ^ g) << 2;
#pragma unroll
                for (int mt = 0; mt < 4; mt++) {
                    const int mb = wm + mt * 16 + g;
                    af[nxt][mt][0] = As[mb * 32 + c0 + t];
                    af[nxt][mt][1] = As[(mb + 8) * 32 + c0 + t];
                    af[nxt][mt][2] = As[mb * 32 + c1 + t];
                    af[nxt][mt][3] = As[(mb + 8) * 32 + c1 + t];
                }
#pragma unroll
                for (int nt = 0; nt < 8; nt++) {
                    const int nb = wn + nt * 8 + g;
                    bf[nxt][nt][0] = Bs[nb * 32 + c0 + t];
                    bf[nxt][nt][1] = Bs[nb * 32 + c1 + t];
                }
            }
#pragma unroll
            for (int mt = 0; mt < 4; mt++)
#pragma unroll
                for (int nt = 0; nt < 8; nt++)
                    mma_tf32(acc[mt][nt], af[cur][mt], bf[cur][nt]);
        }

        if (++stage >= NSTAGE) stage = 0;
    }

#pragma unroll
    for (int mt = 0; mt < 4; mt++) {
#pragma unroll
        for (int nt = 0; nt < 8; nt++) {
            const int row = m0 + wm + mt * 16 + g;
            const int col = n0 + wn + nt * 8 + 2 * t;
            float2 v01 = make_float2(acc[mt][nt][0], acc[mt][nt][1]);
            float2 v23 = make_float2(acc[mt][nt][2], acc[mt][nt][3]);
            *(float2*)&C[(size_t)row * H_DIM + col] = v01;
            *(float2*)&C[(size_t)(row + 8) * H_DIM + col] = v23;
        }
    }
}

// ----------------------------------------------------------------------------
// Round W1+W2 to tf32 (rna) + zero flag counters.
// ----------------------------------------------------------------------------
#define WF4   (H_DIM * H_DIM / 4)

__global__ void __launch_bounds__(256)
round_w(const float* __restrict__ W1, float* __restrict__ w1t,
        const float* __restrict__ W2, float* __restrict__ w2t,
        int* __restrict__ cnt)
{
    if (blockIdx.x == 0 && threadIdx.x < B_DIM)
        cnt[threadIdx.x] = 0;

    int gid = blockIdx.x * blockDim.x + threadIdx.x;
    const float* src = (gid < WF4) ? W1 : W2;
    float* dst = (gid < WF4) ? w1t : w2t;
    int i = (gid < WF4) ? gid : gid - WF4;

    float4 v = *(const float4*)(src + (size_t)i * 4);
    uint32_t o0, o1, o2, o3;
    asm("cvt.rna.tf32.f32 %0, %1;" : "=r"(o0) : "f"(v.x));
    asm("cvt.rna.tf32.f32 %0, %1;" : "=r"(o1) : "f"(v.y));
    asm("cvt.rna.tf32.f32 %0, %1;" : "=r"(o2) : "f"(v.z));
    asm("cvt.rna.tf32.f32 %0, %1;" : "=r"(o3) : "f"(v.w));
    float4 r;
    r.x = __uint_as_float(o0); r.y = __uint_as_float(o1);
    r.z = __uint_as_float(o2); r.w = __uint_as_float(o3);
    *(float4*)(dst + (size_t)i * 4) = r;
}

// ----------------------------------------------------------------------------
// LIF scan (vectorized float4) + flag threshold-marginal lanes.
// ----------------------------------------------------------------------------
__global__ void __launch_bounds__(256)
scan_flag(const float* __restrict__ xp, float* __restrict__ spk,
          int* __restrict__ cnt, int* __restrict__ list)
{
    const int i4 = blockIdx.x * blockDim.x + threadIdx.x;
    if (i4 >= BH / 4) return;

    const float4* xp4 = (const float4*)xp;
    float4* spk4 = (float4*)spk;

    float4 v = make_float4(0.f, 0.f, 0.f, 0.f);
    int flags = 0;
    #pragma unroll 4
    for (int t = 0; t < T_DIM; t++) {
        float4 xv = xp4[(size_t)t * (BH / 4) + i4];
        float4 h;
        h.x = v.x + (xv.x - v.x) * 0.5f;
        h.y = v.y + (xv.y - v.y) * 0.5f;
        h.z = v.z + (xv.z - v.z) * 0.5f;
        h.w = v.w + (xv.w - v.w) * 0.5f;
        flags |= (fabsf(h.x - 1.0f) < DELTA) ? 1 : 0;
        flags |= (fabsf(h.y - 1.0f) < DELTA) ? 2 : 0;
        flags |= (fabsf(h.z - 1.0f) < DELTA) ? 4 : 0;
        flags |= (fabsf(h.w - 1.0f) < DELTA) ? 8 : 0;
        float4 s;
        s.x = (h.x >= 1.0f) ? 1.0f : 0.0f;
        s.y = (h.y >= 1.0f) ? 1.0f : 0.0f;
        s.z = (h.z >= 1.0f) ? 1.0f : 0.0f;
        s.w = (h.w >= 1.0f) ? 1.0f : 0.0f;
        spk4[(size_t)t * (BH / 4) + i4] = s;
        v.x = (h.x >= 1.0f) ? 0.0f : h.x;
        v.y = (h.y >= 1.0f) ? 0.0f : h.y;
        v.z = (h.z >= 1.0f) ? 0.0f : h.z;
        v.w = (h.w >= 1.0f) ? 0.0f : h.w;
    }
    if (flags) {
        const int idx0 = i4 * 4;
        const int b = idx0 >> 10;
        #pragma unroll
        for (int c = 0; c < 4; c++) {
            if (flags & (1 << c)) {
                int p = atomicAdd(&cnt[b], 1);
                list[(b << 10) + p] = (idx0 + c) & 1023;
            }
        }
    }
}

// ----------------------------------------------------------------------------
// fixup_gemm (R12-verbatim): exact fp32 x_proj columns for flagged lanes.
// Grid (B_DIM, 8): y&3 = h-slice (batches of 32, stride 128), y>>2 = t-half.
// ----------------------------------------------------------------------------
__global__ void __launch_bounds__(256)
fixup_gemm(const float* __restrict__ x,
           const float* __restrict__ W1,
           const int* __restrict__ cnt,
           const int* __restrict__ list,
           float* __restrict__ xfix)
{
    __shared__ float Xs[64 * 64];   // 16 KB
    __shared__ float Ws[32 * 64];   //  8 KB
    __shared__ int   hlist[32];

    const int b   = blockIdx.x;
    const int hs  = blockIdx.y & 3;
    const int th  = blockIdx.y >> 2;
    const int tid = threadIdx.x;
    const int jg  = tid & 15;
    const int tg  = tid >> 4;
    const int n   = cnt[b];

    const int boff = b << 10;
    const int tglob0 = th * 64;

    for (int base = hs * 32; base < n; base += 128) {
        if (tid < 32)
            hlist[tid] = (base + tid < n) ? list[boff + base + tid] : 0;
        __syncthreads();

        float acc[2][4];
#pragma unroll
        for (int jj = 0; jj < 2; jj++)
#pragma unroll
            for (int tt = 0; tt < 4; tt++) acc[jj][tt] = 0.0f;

        for (int kc = 0; kc < 16; kc++) {
#pragma unroll
            for (int p = 0; p < 4; p++) {
                int f = tid + p * 256;
                int tl = f >> 4, kq = f & 15;
                float4 v = *(const float4*)(x + (size_t)(tglob0 + tl) * BH
                                            + boff + kc * 64 + kq * 4);
                *(float4*)&Xs[tl * 64 + ((kq ^ (tl & 15)) << 2)] = v;
            }
#pragma unroll
            for (int p = 0; p < 2; p++) {
                int f = tid + p * 256;
                int j = f >> 4, kq = f & 15;
                float4 v = *(const float4*)(W1 + (size_t)hlist[j] * H_DIM
                                            + kc * 64 + kq * 4);
                *(float4*)&Ws[j * 64 + ((kq ^ (j & 15)) << 2)] = v;
            }
            __syncthreads();

#pragma unroll
            for (int kg = 0; kg < 16; kg++) {
                float4 wv0 = *(const float4*)&Ws[jg * 64 + ((kg ^ (jg & 15)) << 2)];
                float4 wv1 = *(const float4*)&Ws[(jg + 16) * 64 + ((kg ^ ((jg + 16) & 15)) << 2)];
                float4 xv[4];
#pragma unroll
                for (int tt = 0; tt < 4; tt++) {
                    int r = 4 * tg + tt;
                    xv[tt] = *(const float4*)&Xs[r * 64 + ((kg ^ (r & 15)) << 2)];
                }
#pragma unroll
                for (int tt = 0; tt < 4; tt++) {
                    acc[0][tt] = fmaf(wv0.x, xv[tt].x, acc[0][tt]);
                    acc[0][tt] = fmaf(wv0.y, xv[tt].y, acc[0][tt]);
                    acc[0][tt] = fmaf(wv0.z, xv[tt].z, acc[0][tt]);
                    acc[0][tt] = fmaf(wv0.w, xv[tt].w, acc[0][tt]);
                    acc[1][tt] = fmaf(wv1.x, xv[tt].x, acc[1][tt]);
                    acc[1][tt] = fmaf(wv1.y, xv[tt].y, acc[1][tt]);
                    acc[1][tt] = fmaf(wv1.z, xv[tt].z, acc[1][tt]);
                    acc[1][tt] = fmaf(wv1.w, xv[tt].w, acc[1][tt]);
                }
            }
            __syncthreads();
        }

#pragma unroll
        for (int jj = 0; jj < 2; jj++) {
            int slot = base + jg + 16 * jj;
            float4 v = make_float4(acc[jj][0], acc[jj][1], acc[jj][2], acc[jj][3]);
            *(float4*)&xfix[((size_t)boff + slot) * T_DIM + tglob0 + 4 * tg] = v;
        }
        __syncthreads();
    }
}

// ----------------------------------------------------------------------------
// fixup_lif: rerun exact LIF for flagged lanes from g_xfix, overwrite spikes.
// ----------------------------------------------------------------------------
__global__ void __launch_bounds__(256)
fixup_lif(const float* __restrict__ xfix,
          const int* __restrict__ cnt,
          const int* __restrict__ list,
          float* __restrict__ spk)
{
    const int idx = blockIdx.x * blockDim.x + threadIdx.x;
    const int b = idx >> 10;
    const int slot = idx & 1023;
    if (b >= B_DIM || slot >= cnt[b]) return;

    const int h = list[(b << 10) + slot];
    const float* xc = xfix + ((size_t)(b << 10) + slot) * T_DIM;
    float v = 0.0f;
    for (int t = 0; t < T_DIM; t++) {
        const float hm = v + (xc[t] - v) * 0.5f;
        const bool fire = (hm >= 1.0f);
        spk[(size_t)t * BH + (b << 10) + h] = fire ? 1.0f : 0.0f;
        v = fire ? 0.0f : hm;
    }
}

// ----------------------------------------------------------------------------
// Launch
// ----------------------------------------------------------------------------
extern "C" void kernel_launch(void* const* d_in, const int* in_sizes, int n_in,
                              void* d_out, int out_size)
{
    const float* x  = (const float*)d_in[0];  // [T,B,H]
    const float* W1 = (const float*)d_in[1];  // [H,H]
    const float* W2 = (const float*)d_in[2];  // [H,H]
    float* out = (float*)d_out;               // [T,B,H]

    float *xf, *xp, *sp, *w1t, *w2t;
    int *cnt, *list;
    cudaGetSymbolAddress((void**)&xf, g_xfix);
    cudaGetSymbolAddress((void**)&xp, g_xproj);
    cudaGetSymbolAddress((void**)&sp, g_spk);
    cudaGetSymbolAddress((void**)&w1t, g_w1t);
    cudaGetSymbolAddress((void**)&w2t, g_w2t);
    cudaGetSymbolAddress((void**)&cnt, g_cnt);
    cudaGetSymbolAddress((void**)&list, g_list);

    cudaFuncSetAttribute(gemm_tf32_mma,
                         cudaFuncAttributeMaxDynamicSharedMemorySize, SMEM_DYN);

    // Round W1/W2 to tf32 (rna) + zero counters (x stays raw; HW RZ-truncates A).
    round_w<<<(2 * WF4) / 256, 256>>>(W1, w1t, W2, w2t, cnt);

    dim3 grid(H_DIM / BN, M_DIM / BM);  // (8, 64)

    // GEMM1 approx (tf32): x_proj ~= x @ W1^T
    gemm_tf32_mma<<<grid, NT_GEMM, SMEM_DYN>>>(x, w1t, xp);

    // LIF scan + flag marginal lanes
    scan_flag<<<(BH / 4) / 256, 256>>>(xp, sp, cnt, list);

    // Exact fp32 recompute of flagged columns, then exact LIF rerun
    fixup_gemm<<<dim3(B_DIM, 8), 256>>>(x, W1, cnt, list, xf);
    fixup_lif<<<(B_DIM * 1024) / 256, 256>>>(xf, cnt, list, sp);

    // GEMM2 (tf32): out = spikes @ W2^T
    gemm_tf32_mma<<<grid, NT_GEMM, SMEM_DYN>>>(sp, w2t, out);
}